// round 1
// baseline (speedup 1.0000x reference)
#include <cuda_runtime.h>
#include <math.h>

// Problem constants
#define BB 32
#define SS 4096
#define HH 1024
#define NSPLIT 32           // splits of S per batch
#define S_SPLIT (SS / NSPLIT)   // 128 rows per block
#define CHUNK 8             // rows held in registers per iteration
#define NCHUNK (S_SPLIT / CHUNK) // 16
#define TPB 256             // threads per block; each owns 4 h-columns (float4)

// Scratch for split-K partials (no runtime allocation allowed)
__device__ float g_cpart[BB * NSPLIT * HH];   // 4 MiB partial contexts
__device__ float g_m[BB * NSPLIT];
__device__ float g_l[BB * NSPLIT];

__global__ __launch_bounds__(TPB)
void attn_pass1(const float* __restrict__ x, const float* __restrict__ w) {
    const int blk = blockIdx.x;
    const int b   = blk / NSPLIT;
    const int sp  = blk % NSPLIT;
    const int t   = threadIdx.x;
    const int wid = t >> 5;
    const int lane = t & 31;

    // base of this block's row range, viewed as float4 (256 float4 per row)
    const float4* __restrict__ x4 =
        (const float4*)(x + ((size_t)b * SS + (size_t)sp * S_SPLIT) * HH);

    const float4 w4 = ((const float4*)w)[t];

    __shared__ float sred[CHUNK * TPB];   // partial dots, 8 KiB
    __shared__ float se[CHUNK];           // per-row energies
    __shared__ float sp_sh[CHUNK];        // per-row softmax numerators

    float4 c = make_float4(0.f, 0.f, 0.f, 0.f);
    float m = -INFINITY;
    float l = 0.f;

    for (int ch = 0; ch < NCHUNK; ch++) {
        const int row0 = ch * CHUNK;
        float4 xr[CHUNK];
        // Batched coalesced loads -> high MLP (8 independent LDG.128 per thread)
        #pragma unroll
        for (int r = 0; r < CHUNK; r++) {
            xr[r] = x4[(size_t)(row0 + r) * (HH / 4) + t];
        }
        // partial dot per row
        #pragma unroll
        for (int r = 0; r < CHUNK; r++) {
            float pd = xr[r].x * w4.x + xr[r].y * w4.y
                     + xr[r].z * w4.z + xr[r].w * w4.w;
            sred[r * TPB + t] = pd;
        }
        __syncthreads();

        // warp `wid` reduces row `wid` (CHUNK == 8 == warps per block)
        {
            const float* rowp = &sred[wid * TPB];
            float s = rowp[lane] + rowp[lane + 32] + rowp[lane + 64] + rowp[lane + 96]
                    + rowp[lane + 128] + rowp[lane + 160] + rowp[lane + 192] + rowp[lane + 224];
            #pragma unroll
            for (int off = 16; off > 0; off >>= 1)
                s += __shfl_xor_sync(0xffffffffu, s, off);
            if (lane == 0) se[wid] = tanhf(s);
        }
        __syncthreads();

        // chunk max (every thread, 8 smem broadcasts — cheap & deterministic)
        float cmax = se[0];
        #pragma unroll
        for (int r = 1; r < CHUNK; r++) cmax = fmaxf(cmax, se[r]);

        if (cmax > m) {
            // rescale only when running max advances (rare after warmup)
            const float scale = expf(m - cmax);   // expf(-inf - x) == 0 for first chunk
            c.x *= scale; c.y *= scale; c.z *= scale; c.w *= scale;
            l *= scale;
            m = cmax;
        }
        // 8 threads compute the 8 exponentials once; broadcast via smem
        if (t < CHUNK) sp_sh[t] = expf(se[t] - m);
        __syncthreads();

        #pragma unroll
        for (int r = 0; r < CHUNK; r++) {
            const float p = sp_sh[r];
            l   += p;                       // redundant per-thread, identical value
            c.x += p * xr[r].x;
            c.y += p * xr[r].y;
            c.z += p * xr[r].z;
            c.w += p * xr[r].w;
        }
        __syncthreads();   // protect sred/sp_sh before next chunk
    }

    const int pidx = b * NSPLIT + sp;
    ((float4*)g_cpart)[(size_t)pidx * (HH / 4) + t] = c;
    if (t == 0) { g_m[pidx] = m; g_l[pidx] = l; }
}

__global__ __launch_bounds__(TPB)
void attn_pass2(float* __restrict__ out) {
    const int b = blockIdx.x;
    const int t = threadIdx.x;

    // global max over splits
    float M = -INFINITY;
    #pragma unroll
    for (int p = 0; p < NSPLIT; p++) M = fmaxf(M, g_m[b * NSPLIT + p]);

    float L = 0.f;
    float4 acc = make_float4(0.f, 0.f, 0.f, 0.f);
    #pragma unroll
    for (int p = 0; p < NSPLIT; p++) {
        const float sc = expf(g_m[b * NSPLIT + p] - M);
        L += g_l[b * NSPLIT + p] * sc;
        const float4 cp = ((const float4*)g_cpart)[(size_t)(b * NSPLIT + p) * (HH / 4) + t];
        acc.x += sc * cp.x;
        acc.y += sc * cp.y;
        acc.z += sc * cp.z;
        acc.w += sc * cp.w;
    }
    const float inv = 1.f / L;
    acc.x *= inv; acc.y *= inv; acc.z *= inv; acc.w *= inv;
    ((float4*)out)[(size_t)b * (HH / 4) + t] = acc;
}

extern "C" void kernel_launch(void* const* d_in, const int* in_sizes, int n_in,
                              void* d_out, int out_size) {
    const float* x = (const float*)d_in[0];   // [B, S, H] fp32
    const float* w = (const float*)d_in[1];   // [H] fp32
    float* out = (float*)d_out;               // [B, H] fp32
    (void)in_sizes; (void)n_in; (void)out_size;

    attn_pass1<<<BB * NSPLIT, TPB>>>(x, w);
    attn_pass2<<<BB, TPB>>>(out);
}

// round 2
// speedup vs baseline: 1.0712x; 1.0712x over previous
#include <cuda_runtime.h>
#include <math.h>

// Problem constants
#define BB 32
#define SS 4096
#define HH 1024
#define NSPLIT 32                 // splits of S per batch
#define S_SPLIT (SS / NSPLIT)     // 128 rows per block
#define CHUNK 8                   // rows held in registers per iteration
#define NCHUNK (S_SPLIT / CHUNK)  // 16
#define TPB 256                   // pass1 threads; each owns 4 h-cols (float4)

// Scratch for split-K partials (no runtime allocation allowed)
__device__ float g_cpart[BB * NSPLIT * HH];   // 4 MiB partial contexts
__device__ float g_m[BB * NSPLIT];
__device__ float g_l[BB * NSPLIT];

__global__ __launch_bounds__(TPB)
void attn_pass1(const float* __restrict__ x, const float* __restrict__ w) {
    const int blk = blockIdx.x;
    const int b   = blk / NSPLIT;
    const int sp  = blk % NSPLIT;
    const int t   = threadIdx.x;
    const int wid = t >> 5;
    const int lane = t & 31;

    const float4* __restrict__ x4 =
        (const float4*)(x + ((size_t)b * SS + (size_t)sp * S_SPLIT) * HH);

    const float4 w4 = ((const float4*)w)[t];

    __shared__ float sred[CHUNK * TPB];   // partial dots, 8 KiB
    __shared__ float se[CHUNK];           // per-row energies
    __shared__ float sp_sh[CHUNK];        // per-row softmax numerators

    float4 c = make_float4(0.f, 0.f, 0.f, 0.f);
    float m = -INFINITY;
    float l = 0.f;

    for (int ch = 0; ch < NCHUNK; ch++) {
        const int row0 = ch * CHUNK;
        float4 xr[CHUNK];
        // Streaming loads (no reuse): evict-first, keep L2 clean. 8 independent
        // LDG.128 per thread -> high MLP.
        #pragma unroll
        for (int r = 0; r < CHUNK; r++) {
            xr[r] = __ldcs(&x4[(size_t)(row0 + r) * (HH / 4) + t]);
        }
        #pragma unroll
        for (int r = 0; r < CHUNK; r++) {
            float pd = xr[r].x * w4.x + xr[r].y * w4.y
                     + xr[r].z * w4.z + xr[r].w * w4.w;
            sred[r * TPB + t] = pd;
        }
        __syncthreads();

        // warp `wid` reduces row `wid` (CHUNK == 8 == warps per block)
        {
            const float* rowp = &sred[wid * TPB];
            float s = rowp[lane] + rowp[lane + 32] + rowp[lane + 64] + rowp[lane + 96]
                    + rowp[lane + 128] + rowp[lane + 160] + rowp[lane + 192] + rowp[lane + 224];
            #pragma unroll
            for (int off = 16; off > 0; off >>= 1)
                s += __shfl_xor_sync(0xffffffffu, s, off);
            if (lane == 0) se[wid] = tanhf(s);
        }
        __syncthreads();

        float cmax = se[0];
        #pragma unroll
        for (int r = 1; r < CHUNK; r++) cmax = fmaxf(cmax, se[r]);

        if (cmax > m) {
            const float scale = expf(m - cmax);   // first chunk: expf(-inf)=0
            c.x *= scale; c.y *= scale; c.z *= scale; c.w *= scale;
            l *= scale;
            m = cmax;
        }
        if (t < CHUNK) sp_sh[t] = expf(se[t] - m);
        __syncthreads();

        #pragma unroll
        for (int r = 0; r < CHUNK; r++) {
            const float p = sp_sh[r];
            l   += p;
            c.x += p * xr[r].x;
            c.y += p * xr[r].y;
            c.z += p * xr[r].z;
            c.w += p * xr[r].w;
        }
        __syncthreads();
    }

    const int pidx = b * NSPLIT + sp;
    ((float4*)g_cpart)[(size_t)pidx * (HH / 4) + t] = c;
    if (t == 0) { g_m[pidx] = m; g_l[pidx] = l; }
}

// Pass 2: combine 32 split partials per batch.
// Grid = BB * HCHUNKS one-warp blocks; each thread owns one float4 column
// slice and loops over splits with 32 independent LDG.128s in flight.
#define HCHUNKS 8
#define F4_PER_B (HH / 4)          // 256
#define F4_PER_CHUNK (F4_PER_B / HCHUNKS)  // 32

__global__ __launch_bounds__(32)
void attn_pass2(float* __restrict__ out) {
    const int b  = blockIdx.x / HCHUNKS;
    const int hc = blockIdx.x % HCHUNKS;
    const int lane = threadIdx.x;
    const int f4idx = hc * F4_PER_CHUNK + lane;

    // global max over splits (broadcast reads, L2-resident)
    float M = -INFINITY;
    #pragma unroll
    for (int p = 0; p < NSPLIT; p++) M = fmaxf(M, g_m[b * NSPLIT + p]);

    float L = 0.f;
    float4 acc = make_float4(0.f, 0.f, 0.f, 0.f);
    #pragma unroll
    for (int p = 0; p < NSPLIT; p++) {
        const float sc = expf(g_m[b * NSPLIT + p] - M);
        L += g_l[b * NSPLIT + p] * sc;
        const float4 cp =
            ((const float4*)g_cpart)[(size_t)(b * NSPLIT + p) * F4_PER_B + f4idx];
        acc.x += sc * cp.x;
        acc.y += sc * cp.y;
        acc.z += sc * cp.z;
        acc.w += sc * cp.w;
    }
    const float inv = 1.f / L;
    acc.x *= inv; acc.y *= inv; acc.z *= inv; acc.w *= inv;
    ((float4*)out)[(size_t)b * F4_PER_B + f4idx] = acc;
}

extern "C" void kernel_launch(void* const* d_in, const int* in_sizes, int n_in,
                              void* d_out, int out_size) {
    const float* x = (const float*)d_in[0];   // [B, S, H] fp32
    const float* w = (const float*)d_in[1];   // [H] fp32
    float* out = (float*)d_out;               // [B, H] fp32
    (void)in_sizes; (void)n_in; (void)out_size;

    attn_pass1<<<BB * NSPLIT, TPB>>>(x, w);
    attn_pass2<<<BB * HCHUNKS, 32>>>(out);
}